// round 1
// baseline (speedup 1.0000x reference)
#include <cuda_runtime.h>

// Problem constants
#define NB    128     // 2*B batch rows
#define MS    512     // mask_size (K + K)
#define DD    256     // feature dim
#define NROWS 32768   // 2B*K rows per input tensor

// Scratch (device globals: allowed; persist across replays so must be re-init each call)
__device__ float g_zn[NB * MS * DD];     // [b][i][d] normalized rows, 64 MB
__device__ float g_rowsum[NB * MS];      // per (b,i): sum_j exp(sim-2)
__device__ float g_pos;                  // sum of cosine(x_r, xp_r)

// ---------------------------------------------------------------------------
// fast 2^x on the FMA pipe (valid for x in ~[-120, 120]; we use [-6, 0.01])
// ---------------------------------------------------------------------------
__device__ __forceinline__ float fexp2(float x) {
    float z = x + 12582912.0f;            // round-to-nearest-int magic (2^23 * 1.5)
    float f = x - (z - 12582912.0f);      // f in [-0.5, 0.5]
    // Taylor of 2^f = e^{f ln2}, degree 5 (rel err ~2.4e-6 on the range)
    float p = fmaf(f, 1.3333558e-3f, 9.6181292e-3f);
    p = fmaf(p, f, 5.5504109e-2f);
    p = fmaf(p, f, 2.4022651e-1f);
    p = fmaf(p, f, 6.9314718e-1f);
    p = fmaf(p, f, 1.0f);
    int sb = ((__float_as_int(z) - 0x4B400000) + 127) << 23;  // 2^n bits
    return p * __int_as_float(sb);
}

// ---------------------------------------------------------------------------
__global__ void k_init() {
    int t = blockIdx.x * blockDim.x + threadIdx.x;
    if (t < NB * MS) g_rowsum[t] = 0.0f;
    if (t == 0) g_pos = 0.0f;
}

// One warp per global row r = i*128 + b. Normalizes x[r] and x_pair[r] into
// g_zn[b][i] and g_zn[b][256+i]; accumulates cosine(x_r, xp_r) for loss_pos.
__global__ __launch_bounds__(256) void k_normalize(const float* __restrict__ x,
                                                   const float* __restrict__ xp) {
    __shared__ float pos_part[8];
    int warp = threadIdx.x >> 5, lane = threadIdx.x & 31;
    int r = (blockIdx.x << 3) + warp;       // 0..32767
    int i = r >> 7;                          // chunk index
    int b = r & 127;                         // batch row
    const float4* xr = (const float4*)x  + (size_t)r * (DD / 4);
    const float4* pr = (const float4*)xp + (size_t)r * (DD / 4);
    float4 a0 = xr[lane], a1 = xr[lane + 32];
    float4 p0 = pr[lane], p1 = pr[lane + 32];

    float sx = a0.x*a0.x + a0.y*a0.y + a0.z*a0.z + a0.w*a0.w
             + a1.x*a1.x + a1.y*a1.y + a1.z*a1.z + a1.w*a1.w;
    float sp = p0.x*p0.x + p0.y*p0.y + p0.z*p0.z + p0.w*p0.w
             + p1.x*p1.x + p1.y*p1.y + p1.z*p1.z + p1.w*p1.w;
    float dp = a0.x*p0.x + a0.y*p0.y + a0.z*p0.z + a0.w*p0.w
             + a1.x*p1.x + a1.y*p1.y + a1.z*p1.z + a1.w*p1.w;
    #pragma unroll
    for (int m = 16; m; m >>= 1) {
        sx += __shfl_xor_sync(0xffffffffu, sx, m);
        sp += __shfl_xor_sync(0xffffffffu, sp, m);
        dp += __shfl_xor_sync(0xffffffffu, dp, m);
    }
    float nx = fmaxf(sqrtf(sx), 1e-8f);
    float np = fmaxf(sqrtf(sp), 1e-8f);
    if (lane == 0) pos_part[warp] = dp / (nx * np);

    float rx = 1.0f / nx, rp = 1.0f / np;
    float4* ox = (float4*)g_zn + ((size_t)b * MS + i) * (DD / 4);
    float4* op = (float4*)g_zn + ((size_t)b * MS + 256 + i) * (DD / 4);
    a0.x *= rx; a0.y *= rx; a0.z *= rx; a0.w *= rx;
    a1.x *= rx; a1.y *= rx; a1.z *= rx; a1.w *= rx;
    p0.x *= rp; p0.y *= rp; p0.z *= rp; p0.w *= rp;
    p1.x *= rp; p1.y *= rp; p1.z *= rp; p1.w *= rp;
    ox[lane] = a0; ox[lane + 32] = a1;
    op[lane] = p0; op[lane + 32] = p1;

    __syncthreads();
    if (threadIdx.x == 0) {
        float s = 0.0f;
        #pragma unroll
        for (int w = 0; w < 8; w++) s += pos_part[w];
        atomicAdd(&g_pos, s);
    }
}

// ---------------------------------------------------------------------------
// Per-b Gram GEMM with fused exp-sum epilogue.
// grid = (4 col-tiles, 4 row-tiles, 128 b); block = 256 threads, 8x8 microtile.
// ---------------------------------------------------------------------------
__global__ __launch_bounds__(256) void k_simexp() {
    // pitch 132 floats = 528 B (16B-multiple -> aligned LDS.128, conflict-light)
    __shared__ float As[32][132];
    __shared__ float Bs[32][132];

    int b  = blockIdx.z;
    int it = blockIdx.y;
    int jt = blockIdx.x;
    const float* Ag = g_zn + ((size_t)b * MS + it * 128) * DD;
    const float* Bg = g_zn + ((size_t)b * MS + jt * 128) * DD;

    int t  = threadIdx.x;
    int tx = t & 15, ty = t >> 4;

    float acc[8][8];
    #pragma unroll
    for (int u = 0; u < 8; u++)
        #pragma unroll
        for (int v = 0; v < 8; v++) acc[u][v] = 0.0f;

    for (int kt = 0; kt < DD; kt += 32) {
        #pragma unroll
        for (int s = 0; s < 4; s++) {
            int idx = t + s * 256;          // 0..1023 float4 slots
            int row = idx >> 3;             // 0..127
            int kq  = idx & 7;              // float4 index within k-chunk
            float4 av = *(const float4*)(Ag + (size_t)row * DD + kt + kq * 4);
            float4 bv = *(const float4*)(Bg + (size_t)row * DD + kt + kq * 4);
            As[kq * 4 + 0][row] = av.x; As[kq * 4 + 1][row] = av.y;
            As[kq * 4 + 2][row] = av.z; As[kq * 4 + 3][row] = av.w;
            Bs[kq * 4 + 0][row] = bv.x; Bs[kq * 4 + 1][row] = bv.y;
            Bs[kq * 4 + 2][row] = bv.z; Bs[kq * 4 + 3][row] = bv.w;
        }
        __syncthreads();
        #pragma unroll
        for (int kk = 0; kk < 32; kk++) {
            float4 A0 = *(const float4*)&As[kk][ty * 8];
            float4 A1 = *(const float4*)&As[kk][ty * 8 + 4];
            float4 B0 = *(const float4*)&Bs[kk][tx * 8];
            float4 B1 = *(const float4*)&Bs[kk][tx * 8 + 4];
            float ar[8] = {A0.x, A0.y, A0.z, A0.w, A1.x, A1.y, A1.z, A1.w};
            float br[8] = {B0.x, B0.y, B0.z, B0.w, B1.x, B1.y, B1.z, B1.w};
            #pragma unroll
            for (int u = 0; u < 8; u++)
                #pragma unroll
                for (int v = 0; v < 8; v++)
                    acc[u][v] = fmaf(ar[u], br[v], acc[u][v]);
        }
        __syncthreads();
    }

    // Epilogue: sim = 2*acc (TEMP=0.5). Accumulate exp(sim-2) = 2^(2.88539*acc - 2.88539),
    // skipping the diagonal. Reduce across tx (16 lanes), atomicAdd per row.
    int gI0 = it * 128 + ty * 8;
    int gJ0 = jt * 128 + tx * 8;
    #pragma unroll
    for (int u = 0; u < 8; u++) {
        int gI = gI0 + u;
        float s = 0.0f;
        #pragma unroll
        for (int v = 0; v < 8; v++) {
            int gJ = gJ0 + v;
            if (gI != gJ) {
                float arg = fmaf(acc[u][v], 2.8853901f, -2.8853901f);
                s += fexp2(arg);
            }
        }
        #pragma unroll
        for (int m = 1; m <= 8; m <<= 1)
            s += __shfl_xor_sync(0xffffffffu, s, m);
        if (tx == 0) atomicAdd(&g_rowsum[b * MS + gI], s);
    }
}

// ---------------------------------------------------------------------------
__global__ void k_finalize(float* __restrict__ out) {
    __shared__ float red[256];
    float s = 0.0f;
    for (int i = threadIdx.x; i < NB * MS; i += 256)
        s += logf(g_rowsum[i]);
    red[threadIdx.x] = s;
    __syncthreads();
    for (int m = 128; m; m >>= 1) {
        if (threadIdx.x < m) red[threadIdx.x] += red[threadIdx.x + m];
        __syncthreads();
    }
    if (threadIdx.x == 0) {
        float loss_neg = red[0] / (float)(NB * MS) + 2.0f;   // add back the shift
        float loss_pos = (g_pos / (float)NROWS) * 2.0f;      // mean(cos)/TEMP
        out[0] = loss_neg - loss_pos;
    }
}

// ---------------------------------------------------------------------------
extern "C" void kernel_launch(void* const* d_in, const int* in_sizes, int n_in,
                              void* d_out, int out_size) {
    const float* x  = (const float*)d_in[0];
    const float* xp = (const float*)d_in[1];
    float* out = (float*)d_out;
    (void)in_sizes; (void)n_in; (void)out_size;

    k_init<<<(NB * MS + 255) / 256, 256>>>();
    k_normalize<<<NROWS / 8, 256>>>(x, xp);
    dim3 g(4, 4, NB);
    k_simexp<<<g, 256>>>();
    k_finalize<<<1, 256>>>(out);
}

// round 14
// speedup vs baseline: 5.4933x; 5.4933x over previous
#include <cuda_runtime.h>
#include <cuda_bf16.h>
#include <cstdint>

#define NB    128     // 2*B
#define MS    512     // mask size
#define DD    256     // feature dim
#define NROWS 32768   // rows per input

// Scratch device globals
__device__ __nv_bfloat16 g_zn[(size_t)NB * MS * DD];   // [b][i][d] normalized bf16 (32 MB)
__device__ float g_rowsum[NB * MS];                    // per (b,i): sum_j exp(sim-2)
__device__ float g_pos;                                // sum of cosine(x, x_pair)
__device__ float g_neg;                                // sum of log(rowsum)

// ---------------------------------------------------------------------------
// fast 2^x on the FMA pipe (arg range here: [-6, 0.01])
// ---------------------------------------------------------------------------
__device__ __forceinline__ float fexp2(float x) {
    float z = x + 12582912.0f;
    float f = x - (z - 12582912.0f);
    float p = fmaf(f, 1.3333558e-3f, 9.6181292e-3f);
    p = fmaf(p, f, 5.5504109e-2f);
    p = fmaf(p, f, 2.4022651e-1f);
    p = fmaf(p, f, 6.9314718e-1f);
    p = fmaf(p, f, 1.0f);
    int sb = ((__float_as_int(z) - 0x4B400000) + 127) << 23;
    return p * __int_as_float(sb);
}

__device__ __forceinline__ uint32_t smem_u32(const void* p) {
    uint32_t a;
    asm("{ .reg .u64 t; cvta.to.shared.u64 t, %1; cvt.u32.u64 %0, t; }" : "=r"(a) : "l"(p));
    return a;
}

#define LDSM_X4(r0, r1, r2, r3, addr) \
    asm volatile("ldmatrix.sync.aligned.m8n8.x4.shared.b16 {%0,%1,%2,%3}, [%4];" \
                 : "=r"(r0), "=r"(r1), "=r"(r2), "=r"(r3) : "r"(addr))

__device__ __forceinline__ void mma16816(float* d, const uint32_t* a, uint32_t b0, uint32_t b1) {
    asm volatile("mma.sync.aligned.m16n8k16.row.col.f32.bf16.bf16.f32 "
                 "{%0,%1,%2,%3}, {%4,%5,%6,%7}, {%8,%9}, {%0,%1,%2,%3};"
                 : "+f"(d[0]), "+f"(d[1]), "+f"(d[2]), "+f"(d[3])
                 : "r"(a[0]), "r"(a[1]), "r"(a[2]), "r"(a[3]), "r"(b0), "r"(b1));
}

// ---------------------------------------------------------------------------
__global__ void k_init() {
    int t = blockIdx.x * 256 + threadIdx.x;          // 64 blocks x 256
    ((float4*)g_rowsum)[t] = make_float4(0.f, 0.f, 0.f, 0.f);
    if (t == 0) { g_pos = 0.0f; g_neg = 0.0f; }
}

// ---------------------------------------------------------------------------
// One warp per global row r = i*128 + b: normalize into bf16 g_zn[b][i] /
// g_zn[b][256+i], accumulate cosine(x_r, xp_r).
// ---------------------------------------------------------------------------
__global__ __launch_bounds__(256) void k_normalize(const float* __restrict__ x,
                                                   const float* __restrict__ xp) {
    __shared__ float pos_part[8];
    int warp = threadIdx.x >> 5, lane = threadIdx.x & 31;
    int r = (blockIdx.x << 3) + warp;
    int i = r >> 7;
    int b = r & 127;
    const float4* xr = (const float4*)x  + (size_t)r * (DD / 4);
    const float4* pr = (const float4*)xp + (size_t)r * (DD / 4);
    float4 a0 = xr[lane], a1 = xr[lane + 32];
    float4 p0 = pr[lane], p1 = pr[lane + 32];

    float sx = a0.x*a0.x + a0.y*a0.y + a0.z*a0.z + a0.w*a0.w
             + a1.x*a1.x + a1.y*a1.y + a1.z*a1.z + a1.w*a1.w;
    float sp = p0.x*p0.x + p0.y*p0.y + p0.z*p0.z + p0.w*p0.w
             + p1.x*p1.x + p1.y*p1.y + p1.z*p1.z + p1.w*p1.w;
    float dp = a0.x*p0.x + a0.y*p0.y + a0.z*p0.z + a0.w*p0.w
             + a1.x*p1.x + a1.y*p1.y + a1.z*p1.z + a1.w*p1.w;
    #pragma unroll
    for (int m = 16; m; m >>= 1) {
        sx += __shfl_xor_sync(0xffffffffu, sx, m);
        sp += __shfl_xor_sync(0xffffffffu, sp, m);
        dp += __shfl_xor_sync(0xffffffffu, dp, m);
    }
    float nx = fmaxf(sqrtf(sx), 1e-8f);
    float np = fmaxf(sqrtf(sp), 1e-8f);
    if (lane == 0) pos_part[warp] = dp / (nx * np);

    float rx = 1.0f / nx, rp = 1.0f / np;
    __nv_bfloat162* ox = (__nv_bfloat162*)(g_zn + ((size_t)b * MS + i) * DD);
    __nv_bfloat162* op = (__nv_bfloat162*)(g_zn + ((size_t)b * MS + 256 + i) * DD);
    ox[lane * 2 + 0]      = __floats2bfloat162_rn(a0.x * rx, a0.y * rx);
    ox[lane * 2 + 1]      = __floats2bfloat162_rn(a0.z * rx, a0.w * rx);
    ox[64 + lane * 2 + 0] = __floats2bfloat162_rn(a1.x * rx, a1.y * rx);
    ox[64 + lane * 2 + 1] = __floats2bfloat162_rn(a1.z * rx, a1.w * rx);
    op[lane * 2 + 0]      = __floats2bfloat162_rn(p0.x * rp, p0.y * rp);
    op[lane * 2 + 1]      = __floats2bfloat162_rn(p0.z * rp, p0.w * rp);
    op[64 + lane * 2 + 0] = __floats2bfloat162_rn(p1.x * rp, p1.y * rp);
    op[64 + lane * 2 + 1] = __floats2bfloat162_rn(p1.z * rp, p1.w * rp);

    __syncthreads();
    if (threadIdx.x == 0) {
        float s = 0.0f;
        #pragma unroll
        for (int w = 0; w < 8; w++) s += pos_part[w];
        atomicAdd(&g_pos, s);
    }
}

// ---------------------------------------------------------------------------
// Symmetric Gram tile kernel. grid (10 tile-pairs, 128 b), 256 threads (8 warps).
// Tile (it, jt), it <= jt: computes S = A(it) * B(jt)^T (128x128, K=256 bf16),
// exp-sums rows (and cols when it != jt, by symmetry) into g_rowsum.
// SMEM: [0..1024) red arrays (sRow 128 + sCol 128 floats), A tile 64KB, B tile 64KB.
// Tiles are stored 512 B/row with 16B-chunk swizzle: chunk' = chunk ^ (row & 7).
// ---------------------------------------------------------------------------
#define SM_A   1024
#define SM_B   (SM_A + 65536)
#define SM_TOTAL (SM_B + 65536)

__constant__ int c_it[10] = {0,0,0,0,1,1,1,2,2,3};
__constant__ int c_jt[10] = {0,1,2,3,1,2,3,2,3,3};

__device__ __forceinline__ void load_tile(char* smem, uint32_t dst,
                                          const __nv_bfloat16* __restrict__ gsrc) {
    int t = threadIdx.x;
    #pragma unroll
    for (int it = 0; it < 16; it++) {
        int idx = it * 256 + t;           // chunk id 0..4095
        int row = idx >> 5;               // 0..127
        int c   = idx & 31;               // 16B chunk within row
        uint4 v = *(const uint4*)((const char*)gsrc + row * 512 + c * 16);
        *(uint4*)(smem + dst + row * 512 + ((c ^ (row & 7)) << 4)) = v;
    }
}

__global__ __launch_bounds__(256, 1) void k_gram() {
    extern __shared__ char smem[];
    uint32_t sb = smem_u32(smem);
    float* sRow = (float*)smem;          // [128]
    float* sCol = (float*)smem + 128;    // [128]
    int t = threadIdx.x, wid = t >> 5, lane = t & 31;
    int pairi = blockIdx.x;
    int b     = blockIdx.y;
    int it = c_it[pairi], jt = c_jt[pairi];
    bool diag = (it == jt);

    if (t < 256) ((float*)smem)[t] = 0.0f;   // zero sRow+sCol

    const __nv_bfloat16* Zb = g_zn + (size_t)b * MS * DD;
    load_tile(smem, SM_A, Zb + (size_t)it * 128 * DD);
    uint32_t sbB = sb + (diag ? SM_A : SM_B);
    if (!diag) load_tile(smem, SM_B, Zb + (size_t)jt * 128 * DD);
    __syncthreads();

    // warp tiling: wm in [0,4) rows of 32, wn in [0,2) cols of 64
    int wm = wid & 3, wn = wid >> 2;
    int r   = lane & 7;
    int sel = lane >> 3;
    int row_off = ((sel & 1) << 3) + r;   // 0..15
    int cb      = sel >> 1;               // chunk select 0/1

    // ldmatrix lane base addresses (row part); per-k-step swizzled chunk added later
    uint32_t aBase0 = sb + SM_A + (uint32_t)(wm * 32 + 0  + row_off) * 512;
    uint32_t aBase1 = sb + SM_A + (uint32_t)(wm * 32 + 16 + row_off) * 512;
    uint32_t bBase0 = sbB + (uint32_t)(wn * 64 + 0  + row_off) * 512;
    uint32_t bBase1 = sbB + (uint32_t)(wn * 64 + 16 + row_off) * 512;
    uint32_t bBase2 = sbB + (uint32_t)(wn * 64 + 32 + row_off) * 512;
    uint32_t bBase3 = sbB + (uint32_t)(wn * 64 + 48 + row_off) * 512;

    float acc[2][8][4];
    #pragma unroll
    for (int f = 0; f < 2; f++)
        #pragma unroll
        for (int n = 0; n < 8; n++)
            #pragma unroll
            for (int q = 0; q < 4; q++) acc[f][n][q] = 0.0f;

    #pragma unroll 4
    for (int ks = 0; ks < 16; ks++) {
        uint32_t koff = (uint32_t)((((ks << 1) | cb) ^ r) << 4);
        uint32_t a[2][4], bb[4][4];
        LDSM_X4(a[0][0], a[0][1], a[0][2], a[0][3], aBase0 + koff);
        LDSM_X4(a[1][0], a[1][1], a[1][2], a[1][3], aBase1 + koff);
        LDSM_X4(bb[0][0], bb[0][1], bb[0][2], bb[0][3], bBase0 + koff);
        LDSM_X4(bb[1][0], bb[1][1], bb[1][2], bb[1][3], bBase1 + koff);
        LDSM_X4(bb[2][0], bb[2][1], bb[2][2], bb[2][3], bBase2 + koff);
        LDSM_X4(bb[3][0], bb[3][1], bb[3][2], bb[3][3], bBase3 + koff);
        #pragma unroll
        for (int f = 0; f < 2; f++)
            #pragma unroll
            for (int n = 0; n < 8; n++) {
                // n even -> regs {0,2} of pair n/2; n odd -> regs {1,3}
                int p = n >> 1, o = n & 1;
                mma16816(acc[f][n], a[f], bb[p][o], bb[p][o + 2]);
            }
    }
    // NOTE: ldmatrix/mma are warp-synchronous; no sync needed before epilogue atomics.

    // Epilogue: e = exp(2*acc - 2) = 2^(2.88539*acc - 2.88539)
    int gRowBase = it * 128, gColBase = jt * 128;
    int lrow = wm * 32 + (lane >> 2);          // local row (lo) base within 128
    int lcol = wn * 64 + 2 * (lane & 3);       // local col base within 128
    float cs[8][2];
    #pragma unroll
    for (int n = 0; n < 8; n++) { cs[n][0] = 0.0f; cs[n][1] = 0.0f; }

    #pragma unroll
    for (int f = 0; f < 2; f++) {
        int row_lo = lrow + f * 16;
        int row_hi = row_lo + 8;
        float rlo = 0.0f, rhi = 0.0f;
        #pragma unroll
        for (int n = 0; n < 8; n++) {
            int col0 = lcol + n * 8, col1 = col0 + 1;
            float e0 = fexp2(fmaf(acc[f][n][0], 2.8853901f, -2.8853901f));
            float e1 = fexp2(fmaf(acc[f][n][1], 2.8853901f, -2.8853901f));
            float e2 = fexp2(fmaf(acc[f][n][2], 2.8853901f, -2.8853901f));
            float e3 = fexp2(fmaf(acc[f][n][3], 2.8853901f, -2.8853901f));
            if (diag) {
                if (row_lo == col0) e0 = 0.0f;
                if (row_lo == col1) e1 = 0.0f;
                if (row_hi == col0) e2 = 0.0f;
                if (row_hi == col1) e3 = 0.0f;
            }
            rlo += e0 + e1;  rhi += e2 + e3;
            cs[n][0] += e0 + e2;  cs[n][1] += e1 + e3;
        }
        // reduce row sums across the 4 lanes sharing a row
        rlo += __shfl_xor_sync(0xffffffffu, rlo, 1);
        rlo += __shfl_xor_sync(0xffffffffu, rlo, 2);
        rhi += __shfl_xor_sync(0xffffffffu, rhi, 1);
        rhi += __shfl_xor_sync(0xffffffffu, rhi, 2);
        if ((lane & 3) == 0) {
            atomicAdd(&sRow[row_lo], rlo);
            atomicAdd(&sRow[row_hi], rhi);
        }
    }
    if (!diag) {
        #pragma unroll
        for (int n = 0; n < 8; n++) {
            float c0 = cs[n][0], c1 = cs[n][1];
            c0 += __shfl_xor_sync(0xffffffffu, c0, 4);
            c0 += __shfl_xor_sync(0xffffffffu, c0, 8);
            c0 += __shfl_xor_sync(0xffffffffu, c0, 16);
            c1 += __shfl_xor_sync(0xffffffffu, c1, 4);
            c1 += __shfl_xor_sync(0xffffffffu, c1, 8);
            c1 += __shfl_xor_sync(0xffffffffu, c1, 16);
            if (lane < 4) {
                atomicAdd(&sCol[lcol + n * 8],     c0);
                atomicAdd(&sCol[lcol + n * 8 + 1], c1);
            }
        }
    }
    __syncthreads();

    if (t < 128) atomicAdd(&g_rowsum[b * MS + gRowBase + t], sRow[t]);
    else if (!diag && t < 256) {
        int i = t - 128;
        atomicAdd(&g_rowsum[b * MS + gColBase + i], sCol[i]);
    }
}

// ---------------------------------------------------------------------------
__global__ void k_logsum() {                 // 64 blocks x 256 threads
    __shared__ float red[256];
    int idx = (blockIdx.x * 256 + threadIdx.x) * 4;
    float4 v = *(const float4*)&g_rowsum[idx];
    float s = __logf(v.x) + __logf(v.y) + __logf(v.z) + __logf(v.w);
    red[threadIdx.x] = s;
    __syncthreads();
    for (int m = 128; m; m >>= 1) {
        if (threadIdx.x < m) red[threadIdx.x] += red[threadIdx.x + m];
        __syncthreads();
    }
    if (threadIdx.x == 0) atomicAdd(&g_neg, red[0]);
}

__global__ void k_fin(float* __restrict__ out) {
    float loss_neg = g_neg / (float)(NB * MS) + 2.0f;   // undo exp shift
    float loss_pos = g_pos / 16384.0f;                  // mean(cos) / TEMP
    out[0] = loss_neg - loss_pos;
}

// ---------------------------------------------------------------------------
extern "C" void kernel_launch(void* const* d_in, const int* in_sizes, int n_in,
                              void* d_out, int out_size) {
    const float* x  = (const float*)d_in[0];
    const float* xp = (const float*)d_in[1];
    float* out = (float*)d_out;
    (void)in_sizes; (void)n_in; (void)out_size;

    cudaFuncSetAttribute(k_gram, cudaFuncAttributeMaxDynamicSharedMemorySize, SM_TOTAL);

    k_init<<<64, 256>>>();
    k_normalize<<<NROWS / 8, 256>>>(x, xp);
    k_gram<<<dim3(10, NB), 256, SM_TOTAL>>>();
    k_logsum<<<64, 256>>>();
    k_fin<<<1, 1>>>(out);
}